// round 10
// baseline (speedup 1.0000x reference)
#include <cuda_runtime.h>
#include <cstdint>

// Problem constants (CostVolume: B=8, C=128, H=128, W=256, d=4)
#define BB   8
#define CC_  128
#define HH   128
#define WW   256
#define SS   9        // 2d+1

#define HB   4        // h rows per CTA
#define WB   32       // w cols per CTA
#define CCH  32       // channel chunk
#define NCH  (CC_ / CCH)          // 4 chunks
#define F2R  (HB + 8)             // 12 halo rows
#define F2P  44                   // padded pitch (floats), keeps 16B align, rotates banks
#define NTHREADS 288              // 9 di * 4 h * 8 wq

#define F1_ELEMS (CCH * HB * WB)          // 4096 floats
#define F2_ELEMS (CCH * F2R * F2P)        // 16896 floats
#define STAGE    (F1_ELEMS + F2_ELEMS)    // 20992 floats
#define SMEM_BYTES (2 * STAGE * 4)        // 167936 B (double buffered)

using u64 = unsigned long long;

__device__ __forceinline__ u64 pack2(float lo, float hi) {
    u64 r;
    asm("mov.b64 %0, {%1, %2};" : "=l"(r) : "f"(lo), "f"(hi));
    return r;
}
__device__ __forceinline__ void unpack2(u64 v, float& lo, float& hi) {
    asm("mov.b64 {%0, %1}, %2;" : "=f"(lo), "=f"(hi) : "l"(v));
}
__device__ __forceinline__ void fma2(u64& acc, u64 a, u64 b) {
    asm("fma.rn.f32x2 %0, %1, %2, %0;" : "+l"(acc) : "l"(a), "l"(b));
}
__device__ __forceinline__ void cp16(uint32_t dst, const void* src, bool ok) {
    int sz = ok ? 16 : 0;
    asm volatile("cp.async.cg.shared.global [%0], [%1], 16, %2;\n"
                 :: "r"(dst), "l"(src), "r"(sz) : "memory");
}

__global__ __launch_bounds__(NTHREADS, 1)
void CostVolume_56745107914783_kernel(const float* __restrict__ f1,
                                      const float* __restrict__ f2,
                                      float* __restrict__ out)
{
    extern __shared__ float smem[];

    const int tid = threadIdx.x;
    const int wq  = tid & 7;          // 0..7  (w quad)
    const int hh  = (tid >> 3) & 3;   // 0..3  (h within tile)
    const int di  = tid >> 5;         // 0..8  (h-shift index)

    const int w0 = blockIdx.x * WB;
    const int h0 = blockIdx.y * HB;
    const int b  = blockIdx.z;

    const float* f1b = f1 + (size_t)b * CC_ * HH * WW;
    const float* f2b = f2 + (size_t)b * CC_ * HH * WW;

    // ---- async-fill of one chunk into one stage buffer ----
    auto issue = [&](int ck, int buf) {
        float* st = smem + buf * STAGE;
        uint32_t st_f1 = (uint32_t)__cvta_generic_to_shared(st);
        uint32_t st_f2 = st_f1 + F1_ELEMS * 4;
        const int c0 = ck * CCH;

        // f1 chunk: [CCH][HB][WB], all in-bounds. 1024 16B granules.
        #pragma unroll 1
        for (int g = tid; g < F1_ELEMS / 4; g += NTHREADS) {
            int c   = g >> 5;
            int rem = g & 31;
            int h   = rem >> 3;
            int wg  = rem & 7;
            const float* src = f1b + ((size_t)(c0 + c) * HH + (h0 + h)) * WW + w0 + wg * 4;
            uint32_t dst = st_f1 + (uint32_t)(((c * HB + h) * WB + wg * 4) * 4);
            cp16(dst, src, true);
        }
        // f2 chunk with halo: [CCH][F2R][40 valid of F2P], 3840 granules,
        // each granule fully in or fully out of bounds -> zfill predicate.
        #pragma unroll 1
        for (int g = tid; g < CCH * F2R * 10; g += NTHREADS) {
            int c   = g / 120;
            int rem = g - c * 120;
            int r   = rem / 10;
            int cg  = rem - r * 10;
            int gh  = h0 + r - 4;
            int gw  = w0 + cg * 4 - 4;
            bool ok = (gh >= 0) && (gh < HH) && (gw >= 0) && (gw + 4 <= WW);
            const float* src = f2b + ((size_t)(c0 + c) * HH + (ok ? gh : 0)) * WW + (ok ? gw : 0);
            uint32_t dst = st_f2 + (uint32_t)(((c * F2R + r) * F2P + cg * 4) * 4);
            cp16(dst, src, ok);
        }
        asm volatile("cp.async.commit_group;" ::: "memory");
    };

    // ---- accumulators: 9 dj * 2 w-pairs, packed f32x2, persist across chunks ----
    u64 acc[SS][2];
    #pragma unroll
    for (int j = 0; j < SS; j++) { acc[j][0] = 0ULL; acc[j][1] = 0ULL; }

    issue(0, 0);

    for (int ck = 0; ck < NCH; ck++) {
        if (ck + 1 < NCH) {
            issue(ck + 1, (ck + 1) & 1);
            asm volatile("cp.async.wait_group 1;" ::: "memory");
        } else {
            asm volatile("cp.async.wait_group 0;" ::: "memory");
        }
        __syncthreads();

        const float* st  = smem + (ck & 1) * STAGE;
        const float* f1p = st + (hh * WB + wq * 4);
        const float* f2p = st + F1_ELEMS + ((hh + di) * F2P + wq * 4);

        #pragma unroll
        for (int c = 0; c < CCH; c++) {
            // f1: 4 outputs' values as two even-aligned pairs (free pairing)
            ulonglong2 pa = *reinterpret_cast<const ulonglong2*>(f1p + c * (HB * WB));

            const float* vp = f2p + c * (F2R * F2P);
            float4 v0 = *reinterpret_cast<const float4*>(vp);
            float4 v1 = *reinterpret_cast<const float4*>(vp + 4);
            float4 v2 = *reinterpret_cast<const float4*>(vp + 8);
            ulonglong2 e01 = *reinterpret_cast<const ulonglong2*>(vp);
            ulonglong2 e23 = *reinterpret_cast<const ulonglong2*>(vp + 4);
            ulonglong2 e45 = *reinterpret_cast<const ulonglong2*>(vp + 8);

            u64 pv[11];
            pv[0] = e01.x; pv[2] = e01.y;
            pv[4] = e23.x; pv[6] = e23.y;
            pv[8] = e45.x; pv[10] = e45.y;
            pv[1] = pack2(v0.y, v0.z);
            pv[3] = pack2(v0.w, v1.x);
            pv[5] = pack2(v1.y, v1.z);
            pv[7] = pack2(v1.w, v2.x);
            pv[9] = pack2(v2.y, v2.z);

            #pragma unroll
            for (int dj = 0; dj < SS; dj++) {
                fma2(acc[dj][0], pa.x, pv[dj]);       // outputs w+0, w+1
                fma2(acc[dj][1], pa.y, pv[dj + 2]);   // outputs w+2, w+3
            }
        }
        __syncthreads();
    }

    // ---- epilogue: scale by 1/C and store ----
    const float scale = 1.0f / (float)CC_;
    #pragma unroll
    for (int dj = 0; dj < SS; dj++) {
        int s = di * SS + dj;
        float a, bv, cv, dv;
        unpack2(acc[dj][0], a, bv);
        unpack2(acc[dj][1], cv, dv);
        float4 o;
        o.x = a  * scale;
        o.y = bv * scale;
        o.z = cv * scale;
        o.w = dv * scale;
        float* dst = out + (((size_t)b * (SS * SS) + s) * HH + (h0 + hh)) * WW + w0 + wq * 4;
        *reinterpret_cast<float4*>(dst) = o;
    }
}

extern "C" void kernel_launch(void* const* d_in, const int* in_sizes, int n_in,
                              void* d_out, int out_size) {
    const float* f1 = (const float*)d_in[0];
    const float* f2 = (const float*)d_in[1];
    float* out = (float*)d_out;

    cudaFuncSetAttribute(CostVolume_56745107914783_kernel,
                         cudaFuncAttributeMaxDynamicSharedMemorySize, SMEM_BYTES);

    dim3 grid(WW / WB, HH / HB, BB);   // 8 x 32 x 8 = 2048 CTAs
    CostVolume_56745107914783_kernel<<<grid, NTHREADS, SMEM_BYTES>>>(f1, f2, out);
}

// round 11
// speedup vs baseline: 1.2433x; 1.2433x over previous
#include <cuda_runtime.h>
#include <cstdint>

// CostVolume: B=8, C=128, H=128, W=256, d=4 -> out (8, 81, 128, 256) fp32
#define BB   8
#define CC_  128
#define HH   128
#define WW   256
#define SS   9

#define HB   8                 // h rows per CTA
#define WB   32                // w cols per CTA
#define CCH  16                // channel chunk
#define NCH  (CC_ / CCH)       // 8 chunks
#define F2R  16                // HB + 8 halo rows
#define F2P  40                // f2 row pitch (floats) = exactly the needed window
#define F1P  32
#define NT   576               // 9 di * 8 hh * 8 wo

#define F1_SLICE (HB * F1P)              // 256 floats per c
#define F1_ELEMS (CCH * F1_SLICE)        // 4096
#define F2_SLICE (F2R * F2P)             // 640 floats per c
#define F2_ELEMS (CCH * F2_SLICE)        // 10240
#define STAGE       (F1_ELEMS + F2_ELEMS)   // 14336 floats
#define STAGE_BYTES (STAGE * 4)             // 57344 B
#define SMEM_BYTES  (2 * STAGE_BYTES)       // 114688 B (double buffered)

#define CHUNK_ELEMS (CCH * HH * WW)      // 524288 elements per c-chunk

using u64 = unsigned long long;

__device__ __forceinline__ u64 pack2(float lo, float hi) {
    u64 r;
    asm("mov.b64 %0, {%1, %2};" : "=l"(r) : "f"(lo), "f"(hi));
    return r;
}
__device__ __forceinline__ void unpack2(u64 v, float& lo, float& hi) {
    asm("mov.b64 {%0, %1}, %2;" : "=f"(lo), "=f"(hi) : "l"(v));
}
__device__ __forceinline__ void fma2(u64& acc, u64 a, u64 b) {
    asm("fma.rn.f32x2 %0, %1, %2, %0;" : "+l"(acc) : "l"(a), "l"(b));
}
__device__ __forceinline__ void cp16(uint32_t dst, const void* src, bool ok) {
    int sz = ok ? 16 : 0;
    asm volatile("cp.async.cg.shared.global [%0], [%1], 16, %2;\n"
                 :: "r"(dst), "l"(src), "r"(sz) : "memory");
}

__global__ __launch_bounds__(NT, 1)
void CostVolume_56745107914783_kernel(const float* __restrict__ f1,
                                      const float* __restrict__ f2,
                                      float* __restrict__ out)
{
    extern __shared__ float smem[];

    const int tid = threadIdx.x;
    const int wo  = tid & 7;          // 0..7  w quad
    const int hh  = (tid >> 3) & 7;   // 0..7  h within tile
    const int di  = tid >> 6;         // 0..8  h-shift index

    const int w0 = blockIdx.x * WB;
    const int h0 = blockIdx.y * HB;
    const int b  = blockIdx.z;

    const float* f1b = f1 + (size_t)b * CC_ * HH * WW;
    const float* f2b = f2 + (size_t)b * CC_ * HH * WW;

    const uint32_t smem_u32 = (uint32_t)__cvta_generic_to_shared(smem);

    // ================= precomputed cp.async addressing =================
    // f1: 1024 granules of 16B: granule g -> row=g/8 (=c*8+hh), cg=g%8.
    //     dst = g*16 bytes. Thread handles g=tid and (if tid<448) g=tid+576
    //     (second granule: row+72 => c+9, same hh => src + 9*HH*WW, affine).
    uint32_t f1_src;
    {
        int row = tid >> 3, cg = tid & 7;
        int c = row >> 3, hr = row & 7;
        f1_src = (uint32_t)(c * HH * WW + (h0 + hr) * WW + w0 + cg * 4);
    }
    const bool f1_has2 = (tid < 448);

    // f2: 2560 granules: g = tid + k*576, k=0..4 (k=4 only for tid<256).
    //     g -> c=g/160, r=(g%160)/10, cg=g%10; fully-in or fully-out granules.
    uint32_t f2_src[5];
    uint32_t f2_dst[5];
    unsigned okm = 0;
    #pragma unroll
    for (int k = 0; k < 5; k++) {
        int g = tid + k * NT;
        if (g < CCH * F2R * 10) {
            int c   = g / 160;
            int rem = g - c * 160;
            int r   = rem / 10;
            int cg  = rem - r * 10;
            int gh  = h0 + r - 4;
            int gw  = w0 + cg * 4 - 4;
            bool ok = (gh >= 0) && (gh < HH) && (gw >= 0) && (gw + 4 <= WW);
            f2_src[k] = ok ? (uint32_t)(c * HH * WW + gh * WW + gw) : 0u;
            f2_dst[k] = (uint32_t)((F1_ELEMS + c * F2_SLICE + r * F2P + cg * 4) * 4);
            okm |= (ok ? 1u : 0u) << k;
        }
    }

    auto issue = [&](int ck, int buf) {
        const uint32_t stb = smem_u32 + buf * STAGE_BYTES;
        const float* f1c = f1b + (size_t)ck * CHUNK_ELEMS;
        const float* f2c = f2b + (size_t)ck * CHUNK_ELEMS;

        cp16(stb + tid * 16, f1c + f1_src, true);
        if (f1_has2)
            cp16(stb + tid * 16 + NT * 16, f1c + f1_src + 9 * HH * WW, true);

        #pragma unroll
        for (int k = 0; k < 4; k++)
            cp16(stb + f2_dst[k], f2c + f2_src[k], (okm >> k) & 1);
        if (tid < 256)
            cp16(stb + f2_dst[4], f2c + f2_src[4], (okm >> 4) & 1);

        asm volatile("cp.async.commit_group;" ::: "memory");
    };

    // ============== accumulators: 9 dj x 2 packed w-pairs ==============
    u64 acc[SS][2];
    #pragma unroll
    for (int j = 0; j < SS; j++) { acc[j][0] = 0ULL; acc[j][1] = 0ULL; }

    const int f1o = hh * F1P + wo * 4;
    const int f2o = F1_ELEMS + (hh + di) * F2P + wo * 4;

    issue(0, 0);

    for (int ck = 0; ck < NCH; ck++) {
        if (ck + 1 < NCH) {
            issue(ck + 1, (ck + 1) & 1);
            asm volatile("cp.async.wait_group 1;" ::: "memory");
        } else {
            asm volatile("cp.async.wait_group 0;" ::: "memory");
        }
        __syncthreads();

        const float* st  = smem + (ck & 1) * STAGE;
        const float* f1p = st + f1o;
        const float* f2p = st + f2o;

        #pragma unroll
        for (int c = 0; c < CCH; c++) {
            ulonglong2 pa = *reinterpret_cast<const ulonglong2*>(f1p + c * F1_SLICE);

            const float* vp = f2p + c * F2_SLICE;
            float4 v0 = *reinterpret_cast<const float4*>(vp);
            float4 v1 = *reinterpret_cast<const float4*>(vp + 4);
            float4 v2 = *reinterpret_cast<const float4*>(vp + 8);
            ulonglong2 e01 = *reinterpret_cast<const ulonglong2*>(vp);
            ulonglong2 e23 = *reinterpret_cast<const ulonglong2*>(vp + 4);
            ulonglong2 e45 = *reinterpret_cast<const ulonglong2*>(vp + 8);

            u64 pv[11];
            pv[0] = e01.x; pv[2]  = e01.y;
            pv[4] = e23.x; pv[6]  = e23.y;
            pv[8] = e45.x; pv[10] = e45.y;
            pv[1] = pack2(v0.y, v0.z);
            pv[3] = pack2(v0.w, v1.x);
            pv[5] = pack2(v1.y, v1.z);
            pv[7] = pack2(v1.w, v2.x);
            pv[9] = pack2(v2.y, v2.z);

            #pragma unroll
            for (int dj = 0; dj < SS; dj++) {
                fma2(acc[dj][0], pa.x, pv[dj]);       // outputs w+0, w+1
                fma2(acc[dj][1], pa.y, pv[dj + 2]);   // outputs w+2, w+3
            }
        }
        __syncthreads();
    }

    // ===================== epilogue: scale + store =====================
    const float scale = 1.0f / (float)CC_;
    #pragma unroll
    for (int dj = 0; dj < SS; dj++) {
        int s = di * SS + dj;
        float a, bv, cv, dv;
        unpack2(acc[dj][0], a, bv);
        unpack2(acc[dj][1], cv, dv);
        float4 o;
        o.x = a  * scale;
        o.y = bv * scale;
        o.z = cv * scale;
        o.w = dv * scale;
        float* dst = out + (((size_t)b * (SS * SS) + s) * HH + (h0 + hh)) * WW + w0 + wo * 4;
        *reinterpret_cast<float4*>(dst) = o;
    }
}

extern "C" void kernel_launch(void* const* d_in, const int* in_sizes, int n_in,
                              void* d_out, int out_size) {
    const float* f1 = (const float*)d_in[0];
    const float* f2 = (const float*)d_in[1];
    float* out = (float*)d_out;

    cudaFuncSetAttribute(CostVolume_56745107914783_kernel,
                         cudaFuncAttributeMaxDynamicSharedMemorySize, SMEM_BYTES);

    dim3 grid(WW / WB, HH / HB, BB);   // 8 x 16 x 8 = 1024 CTAs
    CostVolume_56745107914783_kernel<<<grid, NT, SMEM_BYTES>>>(f1, f2, out);
}